// round 16
// baseline (speedup 1.0000x reference)
#include <cuda_runtime.h>
#include <cuda_fp16.h>

// ScaledDotProductAttention: B=4, H=1, S=4096, D=16, fp32.
// out = [context (B*S*D) | attn (B*S*S)]
// scores = QK^T/4 + (w*link + b); masked(true) -> -1e9; softmax; context = attn @ V.
// R13 lineage (TQ=4, NT=128, 3 CTAs/SM, fp16 K/V scratch, fp16 e buffer,
// predicated EX2, FFMA2). This round: two-pass rebalance —
//   pass 1 fuses ctx accumulation (V loads) into the score pass: 12
//          independent LDGs + 8 FMA chains per iter = max per-warp MLP;
//   pass 2 is a pure dependency-free stream: attn = e * inv.

#define BATCH 4
#define SEQ   4096
#define DIM   16
#define TQ    4            // q-rows per CTA
#define NT    128          // threads per CTA
#define NWARP (NT / 32)

#define SMEM_BYTES (TQ * SEQ * 2)   // 32768 B fp16 e buffer

typedef unsigned long long u64;

// fp16 copies of K and V (512 KB total) — device globals, no allocation.
__device__ __align__(16) __half Ksc[BATCH * SEQ * DIM];
__device__ __align__(16) __half Vsc[BATCH * SEQ * DIM];

__device__ __forceinline__ u64 pk2(float lo, float hi) {
    u64 r; asm("mov.b64 %0, {%1, %2};" : "=l"(r) : "f"(lo), "f"(hi)); return r;
}
__device__ __forceinline__ void upk2(u64 v, float& lo, float& hi) {
    asm("mov.b64 {%0, %1}, %2;" : "=f"(lo), "=f"(hi) : "l"(v));
}
__device__ __forceinline__ u64 fma2(u64 a, u64 b, u64 c) {
    u64 d; asm("fma.rn.f32x2 %0, %1, %2, %3;" : "=l"(d) : "l"(a), "l"(b), "l"(c)); return d;
}
__device__ __forceinline__ u64 mul2(u64 a, u64 b) {
    u64 d; asm("mul.rn.f32x2 %0, %1, %2;" : "=l"(d) : "l"(a), "l"(b)); return d;
}
__device__ __forceinline__ u64 h2tof2(unsigned int h) {
    __half2 hh = *(__half2*)&h;
    float2 f = __half22float2(hh);
    return pk2(f.x, f.y);
}

// -------- prelude: fp32 K/V -> fp16 scratch (1 MB read, graph-capturable) --------
__global__ void cvt_kv_kernel(const float4* __restrict__ K4,
                              const float4* __restrict__ V4)
{
    const int i = blockIdx.x * blockDim.x + threadIdx.x;   // 65536 threads, 4 floats each
    float4 k = K4[i];
    float4 v = V4[i];
    __half2 k0 = __floats2half2_rn(k.x, k.y), k1 = __floats2half2_rn(k.z, k.w);
    __half2 v0 = __floats2half2_rn(v.x, v.y), v1 = __floats2half2_rn(v.z, v.w);
    uint2 kp, vp;
    kp.x = *(unsigned int*)&k0; kp.y = *(unsigned int*)&k1;
    vp.x = *(unsigned int*)&v0; vp.y = *(unsigned int*)&v1;
    ((uint2*)Ksc)[i] = kp;
    ((uint2*)Vsc)[i] = vp;
}

__global__ __launch_bounds__(NT, 3)
void sdpa_fused_kernel(const float* __restrict__ Qp,
                       const int*   __restrict__ Mp,
                       const float* __restrict__ Lp,
                       const float* __restrict__ swp,
                       const float* __restrict__ sbp,
                       float* __restrict__ ctx,
                       float* __restrict__ attn)
{
    extern __shared__ __half scr[];                // TQ*SEQ fp16 e values
    __shared__ float qs[TQ * DIM];
    __shared__ float redw[TQ * NWARP];
    __shared__ float sinv[TQ];
    __shared__ float redc[NWARP * TQ * DIM];       // context partials (1 KB)

    const int tid = threadIdx.x;
    const int wp  = tid >> 5;
    const int ln  = tid & 31;
    const int b   = blockIdx.x / (SEQ / TQ);
    const int q0  = (blockIdx.x % (SEQ / TQ)) * TQ;

    const float LOG2E = 1.44269504088896f;
    const float w2 = (*swp) * LOG2E;
    const float b2 = (*sbp) * LOG2E;
    const float S2 = 0.25f * LOG2E;                // (1/sqrt(16)) * log2e

    if (tid < TQ * DIM)
        qs[tid] = Qp[((size_t)b * SEQ + q0) * DIM + tid];
    __syncthreads();

    u64 q2[TQ * 8];
    #pragma unroll
    for (int q = 0; q < TQ; q++)
        #pragma unroll
        for (int i = 0; i < 8; i++)
            q2[q * 8 + i] = pk2(qs[q * DIM + 2 * i], qs[q * DIM + 2 * i + 1]);

    const uint4*  K16 = (const uint4*)(Ksc + (size_t)b * SEQ * DIM);  // 2 uint4 per row
    const uint4*  V16 = (const uint4*)(Vsc + (size_t)b * SEQ * DIM);
    const float*  Lb  = Lp + (size_t)b * SEQ * SEQ;
    const int*    Mb  = Mp + (size_t)b * SEQ * SEQ;
    float* Ab = attn + (size_t)b * SEQ * SEQ;

    // ===== Pass 1: e -> fp16 smem; row sums; UNNORMALIZED ctx accumulate =====
    float sloc[TQ];
    #pragma unroll
    for (int q = 0; q < TQ; q++) sloc[q] = 0.0f;

    u64 acc2[TQ * 8];
    #pragma unroll
    for (int i = 0; i < TQ * 8; i++) acc2[i] = 0ull;

    #pragma unroll 1
    for (int k = tid; k < SEQ; k += NT) {
        uint4 ka = K16[2 * k];
        uint4 kb = K16[2 * k + 1];
        uint4 va = V16[2 * k];
        uint4 vb = V16[2 * k + 1];
        float lk[TQ];
        int   mk[TQ];
        #pragma unroll
        for (int q = 0; q < TQ; q++) lk[q] = Lb[(size_t)(q0 + q) * SEQ + k];
        #pragma unroll
        for (int q = 0; q < TQ; q++) mk[q] = Mb[(size_t)(q0 + q) * SEQ + k];

        u64 kk[8];
        kk[0] = h2tof2(ka.x); kk[1] = h2tof2(ka.y);
        kk[2] = h2tof2(ka.z); kk[3] = h2tof2(ka.w);
        kk[4] = h2tof2(kb.x); kk[5] = h2tof2(kb.y);
        kk[6] = h2tof2(kb.z); kk[7] = h2tof2(kb.w);
        u64 vv[8];
        vv[0] = h2tof2(va.x); vv[1] = h2tof2(va.y);
        vv[2] = h2tof2(va.z); vv[3] = h2tof2(va.w);
        vv[4] = h2tof2(vb.x); vv[5] = h2tof2(vb.y);
        vv[6] = h2tof2(vb.z); vv[7] = h2tof2(vb.w);

        #pragma unroll
        for (int q = 0; q < TQ; q++) {
            const u64* qq = &q2[q * 8];
            u64 d2 = mul2(qq[0], kk[0]);
            d2 = fma2(qq[1], kk[1], d2);
            d2 = fma2(qq[2], kk[2], d2);
            d2 = fma2(qq[3], kk[3], d2);
            d2 = fma2(qq[4], kk[4], d2);
            d2 = fma2(qq[5], kk[5], d2);
            d2 = fma2(qq[6], kk[6], d2);
            d2 = fma2(qq[7], kk[7], d2);
            float dl, dh;
            upk2(d2, dl, dh);
            float dot = dl + dh;
            float sc2 = fmaf(w2, lk[q], b2);
            sc2 = fmaf(dot, S2, sc2);
            float e = 0.0f;
            if (!mk[q])
                asm("ex2.approx.ftz.f32 %0, %1;" : "=f"(e) : "f"(sc2));
            __half he = __float2half_rn(e);
            scr[q * SEQ + k] = he;
            float ef = __half2float(he);       // the ROUNDED value
            sloc[q] += ef;
            u64 ee = pk2(ef, ef);
            u64* A = &acc2[q * 8];
            A[0] = fma2(ee, vv[0], A[0]);
            A[1] = fma2(ee, vv[1], A[1]);
            A[2] = fma2(ee, vv[2], A[2]);
            A[3] = fma2(ee, vv[3], A[3]);
            A[4] = fma2(ee, vv[4], A[4]);
            A[5] = fma2(ee, vv[5], A[5]);
            A[6] = fma2(ee, vv[6], A[6]);
            A[7] = fma2(ee, vv[7], A[7]);
        }
    }

    // ---- reduce row sums ----
    #pragma unroll
    for (int q = 0; q < TQ; q++) {
        #pragma unroll
        for (int o = 16; o > 0; o >>= 1)
            sloc[q] += __shfl_xor_sync(0xffffffffu, sloc[q], o);
    }
    if (ln == 0) {
        #pragma unroll
        for (int q = 0; q < TQ; q++) redw[q * NWARP + wp] = sloc[q];
    }
    __syncthreads();
    if (tid < TQ) {
        float s = 0.0f;
        #pragma unroll
        for (int t = 0; t < NWARP; t++) s += redw[tid * NWARP + t];
        sinv[tid] = 1.0f / s;
    }
    __syncthreads();

    float inv[TQ];
    #pragma unroll
    for (int q = 0; q < TQ; q++) inv[q] = sinv[q];

    // ---- ctx reduction: unpack + butterfly (64 sums -> lane ln owns {2ln,2ln+1}) ----
    float acc[TQ * DIM];
    #pragma unroll
    for (int i = 0; i < TQ * 8; i++)
        upk2(acc2[i], acc[2 * i], acc[2 * i + 1]);

    #pragma unroll
    for (int o = 16, n = 32; o >= 1; o >>= 1, n >>= 1) {
        const bool hi = (ln & o) != 0;
        #pragma unroll
        for (int i = 0; i < n; i++) {
            float s    = hi ? acc[i] : acc[i + n];
            float r    = __shfl_xor_sync(0xffffffffu, s, o);
            float mine = hi ? acc[i + n] : acc[i];
            acc[i] = mine + r;
        }
    }
    *(float2*)&redc[wp * (TQ * DIM) + 2 * ln] = make_float2(acc[0], acc[1]);
    __syncthreads();

    if (tid < TQ * DIM) {
        float s = 0.0f;
        #pragma unroll
        for (int ww = 0; ww < NWARP; ww++)
            s += redc[ww * (TQ * DIM) + tid];
        const int q = tid >> 4, d = tid & 15;
        ctx[((size_t)b * SEQ + q0 + q) * DIM + d] = s * inv[q];
    }

    // ===== Pass 2: attn = e * inv — dependency-free stream =====
    const __half2* scr2 = (const __half2*)scr;
    #pragma unroll 2
    for (int k = tid; k < SEQ / 2; k += NT) {
        #pragma unroll
        for (int q = 0; q < TQ; q++) {
            __half2 h2 = scr2[q * (SEQ / 2) + k];
            float2 ef = __half22float2(h2);
            *(float2*)&Ab[(size_t)(q0 + q) * SEQ + 2 * k] =
                make_float2(ef.x * inv[q], ef.y * inv[q]);
        }
    }
}

extern "C" void kernel_launch(void* const* d_in, const int* in_sizes, int n_in,
                              void* d_out, int out_size)
{
    const float* Q  = (const float*)d_in[0];
    const float* K  = (const float*)d_in[1];
    const float* V  = (const float*)d_in[2];
    const int*   M  = (const int*)d_in[3];
    const float* L  = (const float*)d_in[4];
    const float* sw = (const float*)d_in[5];
    const float* sb = (const float*)d_in[6];

    float* ctx  = (float*)d_out;                               // B*S*D
    float* attn = (float*)d_out + (size_t)BATCH * SEQ * DIM;   // B*S*S

    // prelude: K/V -> fp16 scratch (262144 elems / 4 per thread)
    cvt_kv_kernel<<<256, 256>>>((const float4*)K, (const float4*)V);

    cudaFuncSetAttribute(sdpa_fused_kernel,
                         cudaFuncAttributeMaxDynamicSharedMemorySize, SMEM_BYTES);

    dim3 grid(BATCH * (SEQ / TQ));
    sdpa_fused_kernel<<<grid, NT, SMEM_BYTES>>>(Q, M, L, sw, sb, ctx, attn);
}

// round 17
// speedup vs baseline: 3.3228x; 3.3228x over previous
#include <cuda_runtime.h>
#include <cuda_fp16.h>

// ScaledDotProductAttention: B=4, H=1, S=4096, D=16, fp32.
// out = [context (B*S*D) | attn (B*S*S)]
// scores = QK^T/4 + (w*link + b); masked(true) -> -1e9; softmax; context = attn @ V.
// R13 structure exactly (TQ=4, NT=128, 3 CTAs/SM, fp16 K/V scratch, fp16 e
// buffer, predicated EX2, FFMA2) with k-pair vectorization: each thread
// handles 2 consecutive k per iter -> L/M as 64-bit loads, scr as half2,
// attn as STG.64, half the loop overhead. Register structure preserved.

#define BATCH 4
#define SEQ   4096
#define DIM   16
#define TQ    4            // q-rows per CTA
#define NT    128          // threads per CTA
#define NWARP (NT / 32)

#define SMEM_BYTES (TQ * SEQ * 2)   // 32768 B fp16 e buffer

typedef unsigned long long u64;

// fp16 copies of K and V (512 KB total) — device globals, no allocation.
__device__ __align__(16) __half Ksc[BATCH * SEQ * DIM];
__device__ __align__(16) __half Vsc[BATCH * SEQ * DIM];

__device__ __forceinline__ u64 pk2(float lo, float hi) {
    u64 r; asm("mov.b64 %0, {%1, %2};" : "=l"(r) : "f"(lo), "f"(hi)); return r;
}
__device__ __forceinline__ void upk2(u64 v, float& lo, float& hi) {
    asm("mov.b64 {%0, %1}, %2;" : "=f"(lo), "=f"(hi) : "l"(v));
}
__device__ __forceinline__ u64 fma2(u64 a, u64 b, u64 c) {
    u64 d; asm("fma.rn.f32x2 %0, %1, %2, %3;" : "=l"(d) : "l"(a), "l"(b), "l"(c)); return d;
}
__device__ __forceinline__ u64 mul2(u64 a, u64 b) {
    u64 d; asm("mul.rn.f32x2 %0, %1, %2;" : "=l"(d) : "l"(a), "l"(b)); return d;
}
__device__ __forceinline__ u64 h2tof2(unsigned int h) {
    __half2 hh = *(__half2*)&h;
    float2 f = __half22float2(hh);
    return pk2(f.x, f.y);
}

// -------- prelude: fp32 K/V -> fp16 scratch (1 MB read, graph-capturable) --------
__global__ void cvt_kv_kernel(const float4* __restrict__ K4,
                              const float4* __restrict__ V4)
{
    const int i = blockIdx.x * blockDim.x + threadIdx.x;   // 65536 threads, 4 floats each
    float4 k = K4[i];
    float4 v = V4[i];
    __half2 k0 = __floats2half2_rn(k.x, k.y), k1 = __floats2half2_rn(k.z, k.w);
    __half2 v0 = __floats2half2_rn(v.x, v.y), v1 = __floats2half2_rn(v.z, v.w);
    uint2 kp, vp;
    kp.x = *(unsigned int*)&k0; kp.y = *(unsigned int*)&k1;
    vp.x = *(unsigned int*)&v0; vp.y = *(unsigned int*)&v1;
    ((uint2*)Ksc)[i] = kp;
    ((uint2*)Vsc)[i] = vp;
}

__device__ __forceinline__ float qkdot(const u64* qq, const u64* kk) {
    u64 d2 = mul2(qq[0], kk[0]);
    d2 = fma2(qq[1], kk[1], d2);
    d2 = fma2(qq[2], kk[2], d2);
    d2 = fma2(qq[3], kk[3], d2);
    d2 = fma2(qq[4], kk[4], d2);
    d2 = fma2(qq[5], kk[5], d2);
    d2 = fma2(qq[6], kk[6], d2);
    d2 = fma2(qq[7], kk[7], d2);
    float dl, dh;
    upk2(d2, dl, dh);
    return dl + dh;
}

__global__ __launch_bounds__(NT, 3)
void sdpa_fused_kernel(const float* __restrict__ Qp,
                       const int*   __restrict__ Mp,
                       const float* __restrict__ Lp,
                       const float* __restrict__ swp,
                       const float* __restrict__ sbp,
                       float* __restrict__ ctx,
                       float* __restrict__ attn)
{
    extern __shared__ __half scr[];                // TQ*SEQ fp16 e values
    __shared__ float qs[TQ * DIM];
    __shared__ float redw[TQ * NWARP];
    __shared__ float sinv[TQ];
    __shared__ float redc[NWARP * TQ * DIM];       // context partials (1 KB)

    const int tid = threadIdx.x;
    const int wp  = tid >> 5;
    const int ln  = tid & 31;
    const int b   = blockIdx.x / (SEQ / TQ);
    const int q0  = (blockIdx.x % (SEQ / TQ)) * TQ;

    const float LOG2E = 1.44269504088896f;
    const float w2 = (*swp) * LOG2E;
    const float b2 = (*sbp) * LOG2E;
    const float S2 = 0.25f * LOG2E;                // (1/sqrt(16)) * log2e

    if (tid < TQ * DIM)
        qs[tid] = Qp[((size_t)b * SEQ + q0) * DIM + tid];
    __syncthreads();

    u64 q2[TQ * 8];
    #pragma unroll
    for (int q = 0; q < TQ; q++)
        #pragma unroll
        for (int i = 0; i < 8; i++)
            q2[q * 8 + i] = pk2(qs[q * DIM + 2 * i], qs[q * DIM + 2 * i + 1]);

    const uint4*  K16 = (const uint4*)(Ksc + (size_t)b * SEQ * DIM);  // 2 uint4 per row
    const uint4*  V16 = (const uint4*)(Vsc + (size_t)b * SEQ * DIM);
    const float*  Lb  = Lp + (size_t)b * SEQ * SEQ;
    const int*    Mb  = Mp + (size_t)b * SEQ * SEQ;
    float* Ab = attn + (size_t)b * SEQ * SEQ;

    // ====== Phase A: e-pairs -> half2 smem; row sums (k-pair per thread) ======
    float sloc[TQ];
    #pragma unroll
    for (int q = 0; q < TQ; q++) sloc[q] = 0.0f;

    for (int k = tid * 2; k < SEQ; k += NT * 2) {
        uint4 ka0 = K16[2 * k];
        uint4 kb0 = K16[2 * k + 1];
        uint4 ka1 = K16[2 * k + 2];
        uint4 kb1 = K16[2 * k + 3];
        float2 lk[TQ];
        int2   mk[TQ];
        #pragma unroll
        for (int q = 0; q < TQ; q++) lk[q] = *(const float2*)&Lb[(size_t)(q0 + q) * SEQ + k];
        #pragma unroll
        for (int q = 0; q < TQ; q++) mk[q] = *(const int2*)&Mb[(size_t)(q0 + q) * SEQ + k];

        u64 kk0[8], kk1[8];
        kk0[0] = h2tof2(ka0.x); kk0[1] = h2tof2(ka0.y);
        kk0[2] = h2tof2(ka0.z); kk0[3] = h2tof2(ka0.w);
        kk0[4] = h2tof2(kb0.x); kk0[5] = h2tof2(kb0.y);
        kk0[6] = h2tof2(kb0.z); kk0[7] = h2tof2(kb0.w);
        kk1[0] = h2tof2(ka1.x); kk1[1] = h2tof2(ka1.y);
        kk1[2] = h2tof2(ka1.z); kk1[3] = h2tof2(ka1.w);
        kk1[4] = h2tof2(kb1.x); kk1[5] = h2tof2(kb1.y);
        kk1[6] = h2tof2(kb1.z); kk1[7] = h2tof2(kb1.w);

        #pragma unroll
        for (int q = 0; q < TQ; q++) {
            const u64* qq = &q2[q * 8];
            float dot0 = qkdot(qq, kk0);
            float dot1 = qkdot(qq, kk1);
            float sc0 = fmaf(dot0, S2, fmaf(w2, lk[q].x, b2));
            float sc1 = fmaf(dot1, S2, fmaf(w2, lk[q].y, b2));
            float e0 = 0.0f, e1 = 0.0f;
            if (!mk[q].x)
                asm("ex2.approx.ftz.f32 %0, %1;" : "=f"(e0) : "f"(sc0));
            if (!mk[q].y)
                asm("ex2.approx.ftz.f32 %0, %1;" : "=f"(e1) : "f"(sc1));
            __half2 he = __floats2half2_rn(e0, e1);
            *(__half2*)&scr[q * SEQ + k] = he;
            float2 ef = __half22float2(he);    // sum the ROUNDED values
            sloc[q] += ef.x + ef.y;
        }
    }

    // ---- reduce row sums ----
    #pragma unroll
    for (int q = 0; q < TQ; q++) {
        #pragma unroll
        for (int o = 16; o > 0; o >>= 1)
            sloc[q] += __shfl_xor_sync(0xffffffffu, sloc[q], o);
    }
    if (ln == 0) {
        #pragma unroll
        for (int q = 0; q < TQ; q++) redw[q * NWARP + wp] = sloc[q];
    }
    __syncthreads();
    if (tid < TQ) {
        float s = 0.0f;
        #pragma unroll
        for (int t = 0; t < NWARP; t++) s += redw[tid * NWARP + t];
        sinv[tid] = 1.0f / s;
    }
    __syncthreads();

    // ====== Phase E: attn = e * inv; ctx accumulate (k-pair per thread) ======
    float inv[TQ];
    #pragma unroll
    for (int q = 0; q < TQ; q++) inv[q] = sinv[q];

    u64 acc2[TQ * 8];
    #pragma unroll
    for (int i = 0; i < TQ * 8; i++) acc2[i] = 0ull;

    for (int k = tid * 2; k < SEQ; k += NT * 2) {
        uint4 va0 = V16[2 * k];
        uint4 vb0 = V16[2 * k + 1];
        uint4 va1 = V16[2 * k + 2];
        uint4 vb1 = V16[2 * k + 3];
        u64 vv0[8], vv1[8];
        vv0[0] = h2tof2(va0.x); vv0[1] = h2tof2(va0.y);
        vv0[2] = h2tof2(va0.z); vv0[3] = h2tof2(va0.w);
        vv0[4] = h2tof2(vb0.x); vv0[5] = h2tof2(vb0.y);
        vv0[6] = h2tof2(vb0.z); vv0[7] = h2tof2(vb0.w);
        vv1[0] = h2tof2(va1.x); vv1[1] = h2tof2(va1.y);
        vv1[2] = h2tof2(va1.z); vv1[3] = h2tof2(va1.w);
        vv1[4] = h2tof2(vb1.x); vv1[5] = h2tof2(vb1.y);
        vv1[6] = h2tof2(vb1.z); vv1[7] = h2tof2(vb1.w);

        #pragma unroll
        for (int q = 0; q < TQ; q++) {
            __half2 he = *(const __half2*)&scr[q * SEQ + k];
            float2 ef = __half22float2(he);
            float a0 = ef.x * inv[q];
            float a1 = ef.y * inv[q];
            *(float2*)&Ab[(size_t)(q0 + q) * SEQ + k] = make_float2(a0, a1);
            u64 aa0 = pk2(a0, a0);
            u64 aa1 = pk2(a1, a1);
            u64* A = &acc2[q * 8];
            #pragma unroll
            for (int i = 0; i < 8; i++) {
                A[i] = fma2(aa0, vv0[i], A[i]);
                A[i] = fma2(aa1, vv1[i], A[i]);
            }
        }
    }

    // ---- unpack + multi-value warp butterfly: 64 sums -> lane ln owns {2ln, 2ln+1} ----
    float acc[TQ * DIM];
    #pragma unroll
    for (int i = 0; i < TQ * 8; i++)
        upk2(acc2[i], acc[2 * i], acc[2 * i + 1]);

    #pragma unroll
    for (int o = 16, n = 32; o >= 1; o >>= 1, n >>= 1) {
        const bool hi = (ln & o) != 0;
        #pragma unroll
        for (int i = 0; i < n; i++) {
            float s    = hi ? acc[i] : acc[i + n];
            float r    = __shfl_xor_sync(0xffffffffu, s, o);
            float mine = hi ? acc[i + n] : acc[i];
            acc[i] = mine + r;
        }
    }
    *(float2*)&redc[wp * (TQ * DIM) + 2 * ln] = make_float2(acc[0], acc[1]);
    __syncthreads();

    if (tid < TQ * DIM) {
        float s = 0.0f;
        #pragma unroll
        for (int ww = 0; ww < NWARP; ww++)
            s += redc[ww * (TQ * DIM) + tid];
        const int q = tid >> 4, d = tid & 15;
        ctx[((size_t)b * SEQ + q0 + q) * DIM + d] = s;
    }
}

extern "C" void kernel_launch(void* const* d_in, const int* in_sizes, int n_in,
                              void* d_out, int out_size)
{
    const float* Q  = (const float*)d_in[0];
    const float* K  = (const float*)d_in[1];
    const float* V  = (const float*)d_in[2];
    const int*   M  = (const int*)d_in[3];
    const float* L  = (const float*)d_in[4];
    const float* sw = (const float*)d_in[5];
    const float* sb = (const float*)d_in[6];

    float* ctx  = (float*)d_out;                               // B*S*D
    float* attn = (float*)d_out + (size_t)BATCH * SEQ * DIM;   // B*S*S

    // prelude: K/V -> fp16 scratch (262144 elems / 4 per thread)
    cvt_kv_kernel<<<256, 256>>>((const float4*)K, (const float4*)V);

    cudaFuncSetAttribute(sdpa_fused_kernel,
                         cudaFuncAttributeMaxDynamicSharedMemorySize, SMEM_BYTES);

    dim3 grid(BATCH * (SEQ / TQ));
    sdpa_fused_kernel<<<grid, NT, SMEM_BYTES>>>(Q, M, L, sw, sb, ctx, attn);
}